// round 3
// baseline (speedup 1.0000x reference)
#include <cuda_runtime.h>
#include <cstdint>

// Problem constants (fixed by the reference)
#define NN   100000
#define NE   1600000
#define CH   128
#define NG   512
#define TOT  (NE + NN)          // edges + self loops
#define SCAN_T 1024
#define NB_SCAN ((NN + SCAN_T - 1) / SCAN_T)   // 98

// ---------------- scratch (static __device__ allocations; allowed) ----------
__device__ float g_t[(size_t)NN * CH];     // post-GEMM features
__device__ float g_h[(size_t)NN * CH];     // post-aggregation features
__device__ float g_pool[NG * CH];          // global_add_pool accumulator
__device__ float g_dinv[NN];
__device__ int   g_cnt[NN];
__device__ int   g_rowptr[NN + 1];
__device__ int   g_fill[NN];
__device__ int2  g_edge[TOT];              // .x = src col, .y = weight bits
__device__ int   g_bsum[NB_SCAN];
__device__ int   g_boff[NB_SCAN];
__device__ int   g_ei64;                   // 1 if edge_index is int64, else int32
__device__ int   g_b64;                    // 1 if batch is int64, else int32

// ---------------- dtype-agnostic index load ---------------------------------
__device__ __forceinline__ int ld_idx(const void* __restrict__ p, int i, int is64) {
    if (is64) return (int)((const long long*)p)[i];
    return ((const int*)p)[i];
}

// Detect int64 vs int32: little-endian int64 of small values has zero high
// words at odd 32-bit positions; int32 node-id data has nonzero odd words
// (P(all 64 sampled == 0) ~ 1e-320). Word indices stay in-bounds under both
// interpretations.
__global__ void k_detect(const int* __restrict__ ei32, const int* __restrict__ b32) {
    if (threadIdx.x != 0 || blockIdx.x != 0) return;
    int e64 = 1;
    for (int k = 0; k < 64; k++)
        if (ei32[2 * k + 1] != 0) { e64 = 0; break; }
    g_ei64 = e64;
    int b64 = 1;
    // sample odd words near the middle: int32 batch values there are ~256 (nonzero)
    for (int k = 0; k < 64; k++)
        if (b32[2 * (25000 + k) + 1] != 0) { b64 = 0; break; }
    g_b64 = b64;
}

// ---------------- f32x2 helpers (Blackwell packed fp32 — 2x FFMA rate) ------
__device__ __forceinline__ void ffma2(unsigned long long& d,
                                      unsigned long long a,
                                      unsigned long long b) {
    asm volatile("fma.rn.f32x2 %0, %1, %2, %0;" : "+l"(d) : "l"(a), "l"(b));
}
__device__ __forceinline__ unsigned long long pack2(float lo, float hi) {
    unsigned long long r;
    asm("mov.b64 %0, {%1, %2};" : "=l"(r) : "f"(lo), "f"(hi));
    return r;
}
__device__ __forceinline__ void unpack2(unsigned long long v, float& lo, float& hi) {
    asm("mov.b64 {%0, %1}, %2;" : "=f"(lo), "=f"(hi) : "l"(v));
}

// ---------------- graph preprocessing ---------------------------------------
__global__ void k_init() {
    int i = blockIdx.x * blockDim.x + threadIdx.x;
    if (i < NN) g_cnt[i] = 1;                 // self loop contributes 1 to degree
    if (i < NG * CH) g_pool[i] = 0.0f;
}

__global__ void k_degree(const void* __restrict__ ei) {
    int e = blockIdx.x * blockDim.x + threadIdx.x;
    if (e < NE) {
        int is64 = g_ei64;
        int d = ld_idx(ei, NE + e, is64);
        atomicAdd(&g_cnt[d], 1);
    }
}

__global__ void k_dinv() {
    int i = blockIdx.x * blockDim.x + threadIdx.x;
    if (i < NN) g_dinv[i] = rsqrtf((float)g_cnt[i]);
}

// block-local exclusive scan of g_cnt -> g_rowptr (partial), block sums -> g_bsum
__global__ void k_scan1() {
    __shared__ int ws[32];
    int tid = threadIdx.x;
    int i = blockIdx.x * SCAN_T + tid;
    int v = (i < NN) ? g_cnt[i] : 0;
    int lane = tid & 31, wid = tid >> 5;
    int x = v;
    #pragma unroll
    for (int o = 1; o < 32; o <<= 1) {
        int y = __shfl_up_sync(0xffffffffu, x, o);
        if (lane >= o) x += y;
    }
    if (lane == 31) ws[wid] = x;
    __syncthreads();
    if (wid == 0) {
        int s = ws[lane];
        #pragma unroll
        for (int o = 1; o < 32; o <<= 1) {
            int y = __shfl_up_sync(0xffffffffu, s, o);
            if (lane >= o) s += y;
        }
        ws[lane] = s;
    }
    __syncthreads();
    int off = wid ? ws[wid - 1] : 0;
    int incl = x + off;
    if (i < NN) g_rowptr[i] = incl - v;       // exclusive within block
    if (tid == SCAN_T - 1) g_bsum[blockIdx.x] = incl;
}

// exclusive scan of the 98 block sums
__global__ void k_scan2() {
    __shared__ int ws[4];
    int tid = threadIdx.x;
    int v = (tid < NB_SCAN) ? g_bsum[tid] : 0;
    int lane = tid & 31, wid = tid >> 5;
    int x = v;
    #pragma unroll
    for (int o = 1; o < 32; o <<= 1) {
        int y = __shfl_up_sync(0xffffffffu, x, o);
        if (lane >= o) x += y;
    }
    if (lane == 31) ws[wid] = x;
    __syncthreads();
    if (tid == 0) {
        int s = 0;
        #pragma unroll
        for (int k = 0; k < 4; k++) { int t = ws[k]; ws[k] = s; s += t; }
    }
    __syncthreads();
    if (tid < NB_SCAN) g_boff[tid] = x - v + ws[wid];
}

// finalize rowptr, write self-loop edge, init fill cursors
__global__ void k_scan3() {
    int tid = threadIdx.x;
    int i = blockIdx.x * SCAN_T + tid;
    if (i < NN) {
        int rp = g_rowptr[i] + g_boff[blockIdx.x];
        g_rowptr[i] = rp;
        float di = g_dinv[i];
        g_edge[rp] = make_int2(i, __float_as_int(di * di));
        g_fill[i] = rp + 1;
    }
    if (i == 0) g_rowptr[NN] = TOT;
}

__global__ void k_fill(const void* __restrict__ ei) {
    int e = blockIdx.x * blockDim.x + threadIdx.x;
    if (e < NE) {
        int is64 = g_ei64;
        int s = ld_idx(ei, e, is64);
        int d = ld_idx(ei, NE + e, is64);
        int pos = atomicAdd(&g_fill[d], 1);
        g_edge[pos] = make_int2(s, __float_as_int(g_dinv[s] * g_dinv[d]));
    }
}

// ---------------- SGEMM: g_t[N,128] = A[N,128] @ W[128,128] (f32x2) ---------
// A == nullptr means "read from g_h" (avoids host-side symbol lookup).
__global__ __launch_bounds__(256, 2)
void k_gemm(const float* __restrict__ A, const float* __restrict__ W) {
    __shared__ float As[8][128];
    __shared__ float Bs[8][128];
    const float* __restrict__ Abase = (A != nullptr) ? A : (const float*)g_h;

    int tid = threadIdx.x;
    int rowBase = blockIdx.x * 128;

    int arow = tid >> 1;              // 0..127
    int ak   = (tid & 1) * 4;         // 0 or 4
    int brow = tid >> 5;              // 0..7
    int bcol = (tid & 31) * 4;        // 0..124

    int ty = tid >> 4, tx = tid & 15;
    int r0 = ty * 8, c0 = tx * 8;

    unsigned long long acc[8][4];
    #pragma unroll
    for (int i = 0; i < 8; i++)
        #pragma unroll
        for (int j = 0; j < 4; j++) acc[i][j] = 0ull;  // bits(0,0) == (0.f,0.f)

    int grow = rowBase + arow;
    bool avalid = grow < NN;
    const float* Arow = Abase + (size_t)(avalid ? grow : 0) * CH;

    #pragma unroll 1
    for (int kt = 0; kt < CH; kt += 8) {
        float4 av = avalid ? *(const float4*)(Arow + kt + ak)
                           : make_float4(0.f, 0.f, 0.f, 0.f);
        As[ak + 0][arow] = av.x;
        As[ak + 1][arow] = av.y;
        As[ak + 2][arow] = av.z;
        As[ak + 3][arow] = av.w;
        *(float4*)&Bs[brow][bcol] = *(const float4*)(W + (size_t)(kt + brow) * CH + bcol);
        __syncthreads();

        #pragma unroll
        for (int k = 0; k < 8; k++) {
            float4 bv0 = *(const float4*)&Bs[k][c0];
            float4 bv1 = *(const float4*)&Bs[k][c0 + 4];
            unsigned long long bf[4];
            bf[0] = pack2(bv0.x, bv0.y);
            bf[1] = pack2(bv0.z, bv0.w);
            bf[2] = pack2(bv1.x, bv1.y);
            bf[3] = pack2(bv1.z, bv1.w);
            #pragma unroll
            for (int i = 0; i < 8; i++) {
                float a = As[k][r0 + i];
                unsigned long long ap = pack2(a, a);
                ffma2(acc[i][0], ap, bf[0]);
                ffma2(acc[i][1], ap, bf[1]);
                ffma2(acc[i][2], ap, bf[2]);
                ffma2(acc[i][3], ap, bf[3]);
            }
        }
        __syncthreads();
    }

    #pragma unroll
    for (int i = 0; i < 8; i++) {
        int row = rowBase + r0 + i;
        if (row < NN) {
            float o0, o1, o2, o3, o4, o5, o6, o7;
            unpack2(acc[i][0], o0, o1);
            unpack2(acc[i][1], o2, o3);
            unpack2(acc[i][2], o4, o5);
            unpack2(acc[i][3], o6, o7);
            float* dst = g_t + (size_t)row * CH + c0;
            *(float4*)(dst)     = make_float4(o0, o1, o2, o3);
            *(float4*)(dst + 4) = make_float4(o4, o5, o6, o7);
        }
    }
}

// ---------------- aggregation: h[i] = ReLU(sum_j w_j * t[col_j] + b) --------
// one warp per node; lane owns 4 channels (float4)
template <bool LAST>
__global__ __launch_bounds__(256)
void k_agg(const float* __restrict__ bias, const void* __restrict__ batch) {
    int node = (blockIdx.x * blockDim.x + threadIdx.x) >> 5;
    int lane = threadIdx.x & 31;
    if (node >= NN) return;
    int beg = g_rowptr[node];
    int end = g_rowptr[node + 1];
    int co = lane * 4;

    float ax = 0.f, ay = 0.f, az = 0.f, aw = 0.f;

    int j = beg;
    for (; j + 2 <= end; j += 2) {
        int2 e0 = g_edge[j];
        int2 e1 = g_edge[j + 1];
        float4 v0 = *(const float4*)(g_t + (size_t)e0.x * CH + co);
        float4 v1 = *(const float4*)(g_t + (size_t)e1.x * CH + co);
        float w0 = __int_as_float(e0.y);
        float w1 = __int_as_float(e1.y);
        ax = fmaf(w0, v0.x, ax); ay = fmaf(w0, v0.y, ay);
        az = fmaf(w0, v0.z, az); aw = fmaf(w0, v0.w, aw);
        ax = fmaf(w1, v1.x, ax); ay = fmaf(w1, v1.y, ay);
        az = fmaf(w1, v1.z, az); aw = fmaf(w1, v1.w, aw);
    }
    if (j < end) {
        int2 e0 = g_edge[j];
        float4 v0 = *(const float4*)(g_t + (size_t)e0.x * CH + co);
        float w0 = __int_as_float(e0.y);
        ax = fmaf(w0, v0.x, ax); ay = fmaf(w0, v0.y, ay);
        az = fmaf(w0, v0.z, az); aw = fmaf(w0, v0.w, aw);
    }

    float4 b = *(const float4*)(bias + co);
    ax = fmaxf(ax + b.x, 0.f);
    ay = fmaxf(ay + b.y, 0.f);
    az = fmaxf(az + b.z, 0.f);
    aw = fmaxf(aw + b.w, 0.f);

    *(float4*)(g_h + (size_t)node * CH + co) = make_float4(ax, ay, az, aw);

    if (LAST) {
        int g = ld_idx(batch, node, g_b64);
        float* pp = g_pool + g * CH + co;
        atomicAdd(pp + 0, ax);
        atomicAdd(pp + 1, ay);
        atomicAdd(pp + 2, az);
        atomicAdd(pp + 3, aw);
    }
}

// ---------------- head: out[g] = dot(pool[g], head_w) + head_b --------------
__global__ void k_head(const float* __restrict__ hw, const float* __restrict__ hb,
                       float* __restrict__ out) {
    int gid = (blockIdx.x * blockDim.x + threadIdx.x) >> 5;
    int lane = threadIdx.x & 31;
    if (gid >= NG) return;
    const float* p = g_pool + gid * CH;
    float s = p[lane]      * hw[lane]
            + p[lane + 32] * hw[lane + 32]
            + p[lane + 64] * hw[lane + 64]
            + p[lane + 96] * hw[lane + 96];
    #pragma unroll
    for (int o = 16; o; o >>= 1) s += __shfl_xor_sync(0xffffffffu, s, o);
    if (lane == 0) out[gid] = s + hb[0];
}

// ---------------- launch ----------------------------------------------------
extern "C" void kernel_launch(void* const* d_in, const int* in_sizes, int n_in,
                              void* d_out, int out_size) {
    // Identify inputs by UNIQUE element counts (order-proof):
    //   x        : 100000*128 = 12800000  (float32)
    //   edge_idx : 2*1600000  =  3200000  (int32 or int64 — detected on device)
    //   batch    : 100000                 (int32 or int64 — detected on device)
    //   Ws       : 3*128*128  =    49152  (float32)
    //   bs       : 3*128      =      384  (float32)
    //   head_w   : 128                    (float32)
    //   head_b   : 1                      (float32)
    const float* x     = nullptr;
    const void*  ei    = nullptr;
    const void*  batch = nullptr;
    const float* Ws    = nullptr;
    const float* bs    = nullptr;
    const float* hw    = nullptr;
    const float* hb    = nullptr;
    for (int i = 0; i < n_in; i++) {
        switch (in_sizes[i]) {
            case 12800000: x     = (const float*)d_in[i]; break;
            case 3200000:  ei    = d_in[i];               break;
            case 100000:   batch = d_in[i];               break;
            case 49152:    Ws    = (const float*)d_in[i]; break;
            case 384:      bs    = (const float*)d_in[i]; break;
            case 128:      hw    = (const float*)d_in[i]; break;
            case 1:        hb    = (const float*)d_in[i]; break;
            default: break;
        }
    }
    float* out = (float*)d_out;

    const int T = 256;
    int gN = (NN + T - 1) / T;
    int gE = (NE + T - 1) / T;
    int gGemm = (NN + 127) / 128;
    int gAgg = (NN + 7) / 8;           // 8 warps per 256-thread block

    // dtype detection, then build normalization + CSR (once, reused 3x)
    k_detect<<<1, 32>>>((const int*)ei, (const int*)batch);
    k_init<<<gN, T>>>();
    k_degree<<<gE, T>>>(ei);
    k_dinv<<<gN, T>>>();
    k_scan1<<<NB_SCAN, SCAN_T>>>();
    k_scan2<<<1, 128>>>();
    k_scan3<<<NB_SCAN, SCAN_T>>>();
    k_fill<<<gE, T>>>(ei);

    // layer 0
    k_gemm<<<gGemm, T>>>(x, Ws + 0 * CH * CH);
    k_agg<false><<<gAgg, T>>>(bs + 0 * CH, batch);
    // layer 1 (A=nullptr -> read g_h)
    k_gemm<<<gGemm, T>>>(nullptr, Ws + 1 * CH * CH);
    k_agg<false><<<gAgg, T>>>(bs + 1 * CH, batch);
    // layer 2 (fused global_add_pool in epilogue)
    k_gemm<<<gGemm, T>>>(nullptr, Ws + 2 * CH * CH);
    k_agg<true><<<gAgg, T>>>(bs + 2 * CH, batch);

    // readout head
    k_head<<<(NG * 32 + T - 1) / T, T>>>(hw, hb, out);
}

// round 4
// speedup vs baseline: 1.3578x; 1.3578x over previous
#include <cuda_runtime.h>
#include <cstdint>

// Problem constants (fixed by the reference)
#define NN   100000
#define NE   1600000
#define CH   128
#define NG   512
#define TOT  (NE + NN)          // edges + self loops
#define SCAN_T 1024
#define NB_SCAN ((NN + SCAN_T - 1) / SCAN_T)   // 98
#define GROWS 64                 // GEMM rows per block

// ---------------- scratch (static __device__ allocations; allowed) ----------
__device__ float g_t[(size_t)NN * CH];     // post-GEMM features
__device__ float g_h[(size_t)NN * CH];     // post-aggregation features
__device__ float g_pool[NG * CH];          // global_add_pool accumulator
__device__ float g_dinv[NN];
__device__ int   g_cnt[NN];
__device__ int   g_rowptr[NN + 1];
__device__ int   g_fill[NN];
__device__ int2  g_edge[TOT];              // .x = src col, .y = weight bits
__device__ int   g_bsum[NB_SCAN];
__device__ int   g_boff[NB_SCAN];
__device__ int   g_ei64;                   // 1 if edge_index is int64, else int32
__device__ int   g_b64;                    // 1 if batch is int64, else int32
// B fragments in mma register order, tf32-converted:
// index = ((layer*16 + kc)*16 + nt)*32 + lane  -> uint2 {b0,b1}
__device__ uint2 g_wfrag[3 * 16 * 16 * 32];

// ---------------- dtype-agnostic index load ---------------------------------
__device__ __forceinline__ int ld_idx(const void* __restrict__ p, int i, int is64) {
    if (is64) return (int)((const long long*)p)[i];
    return ((const int*)p)[i];
}

// Detect int64 vs int32 (little-endian: int64 of small values has zero odd words).
__global__ void k_detect(const int* __restrict__ ei32, const int* __restrict__ b32) {
    if (threadIdx.x != 0 || blockIdx.x != 0) return;
    int e64 = 1;
    for (int k = 0; k < 64; k++)
        if (ei32[2 * k + 1] != 0) { e64 = 0; break; }
    g_ei64 = e64;
    int b64 = 1;
    for (int k = 0; k < 64; k++)
        if (b32[2 * (25000 + k) + 1] != 0) { b64 = 0; break; }
    g_b64 = b64;
}

// ---------------- graph preprocessing ---------------------------------------
__global__ void k_init() {
    int i = blockIdx.x * blockDim.x + threadIdx.x;
    if (i < NN) g_cnt[i] = 1;                 // self loop contributes 1 to degree
    if (i < NG * CH) g_pool[i] = 0.0f;
}

__global__ void k_degree(const void* __restrict__ ei) {
    int e = blockIdx.x * blockDim.x + threadIdx.x;
    if (e < NE) {
        int is64 = g_ei64;
        int d = ld_idx(ei, NE + e, is64);
        atomicAdd(&g_cnt[d], 1);
    }
}

__global__ void k_dinv() {
    int i = blockIdx.x * blockDim.x + threadIdx.x;
    if (i < NN) g_dinv[i] = rsqrtf((float)g_cnt[i]);
}

// block-local exclusive scan of g_cnt -> g_rowptr (partial), block sums -> g_bsum
__global__ void k_scan1() {
    __shared__ int ws[32];
    int tid = threadIdx.x;
    int i = blockIdx.x * SCAN_T + tid;
    int v = (i < NN) ? g_cnt[i] : 0;
    int lane = tid & 31, wid = tid >> 5;
    int x = v;
    #pragma unroll
    for (int o = 1; o < 32; o <<= 1) {
        int y = __shfl_up_sync(0xffffffffu, x, o);
        if (lane >= o) x += y;
    }
    if (lane == 31) ws[wid] = x;
    __syncthreads();
    if (wid == 0) {
        int s = ws[lane];
        #pragma unroll
        for (int o = 1; o < 32; o <<= 1) {
            int y = __shfl_up_sync(0xffffffffu, s, o);
            if (lane >= o) s += y;
        }
        ws[lane] = s;
    }
    __syncthreads();
    int off = wid ? ws[wid - 1] : 0;
    int incl = x + off;
    if (i < NN) g_rowptr[i] = incl - v;       // exclusive within block
    if (tid == SCAN_T - 1) g_bsum[blockIdx.x] = incl;
}

// exclusive scan of the 98 block sums
__global__ void k_scan2() {
    __shared__ int ws[4];
    int tid = threadIdx.x;
    int v = (tid < NB_SCAN) ? g_bsum[tid] : 0;
    int lane = tid & 31, wid = tid >> 5;
    int x = v;
    #pragma unroll
    for (int o = 1; o < 32; o <<= 1) {
        int y = __shfl_up_sync(0xffffffffu, x, o);
        if (lane >= o) x += y;
    }
    if (lane == 31) ws[wid] = x;
    __syncthreads();
    if (tid == 0) {
        int s = 0;
        #pragma unroll
        for (int k = 0; k < 4; k++) { int t = ws[k]; ws[k] = s; s += t; }
    }
    __syncthreads();
    if (tid < NB_SCAN) g_boff[tid] = x - v + ws[wid];
}

// finalize rowptr, write self-loop edge, init fill cursors
__global__ void k_scan3() {
    int tid = threadIdx.x;
    int i = blockIdx.x * SCAN_T + tid;
    if (i < NN) {
        int rp = g_rowptr[i] + g_boff[blockIdx.x];
        g_rowptr[i] = rp;
        float di = g_dinv[i];
        g_edge[rp] = make_int2(i, __float_as_int(di * di));
        g_fill[i] = rp + 1;
    }
    if (i == 0) g_rowptr[NN] = TOT;
}

__global__ void k_fill(const void* __restrict__ ei) {
    int e = blockIdx.x * blockDim.x + threadIdx.x;
    if (e < NE) {
        int is64 = g_ei64;
        int s = ld_idx(ei, e, is64);
        int d = ld_idx(ei, NE + e, is64);
        int pos = atomicAdd(&g_fill[d], 1);
        g_edge[pos] = make_int2(s, __float_as_int(g_dinv[s] * g_dinv[d]));
    }
}

// ---------------- W prepack: B fragments for mma.m16n8k8.tf32 ----------------
// b0 = W[kc*8 + (lane&3)][nt*8 + (lane>>2)], b1 = same with k+4
__global__ void k_wfrag(const float* __restrict__ Ws) {
    int idx = blockIdx.x * 256 + threadIdx.x;
    if (idx >= 3 * 16 * 16 * 32) return;
    int lane = idx & 31;
    int nt   = (idx >> 5) & 15;
    int kc   = (idx >> 9) & 15;
    int l    = idx >> 13;
    const float* W = Ws + (size_t)l * CH * CH;
    int k0 = kc * 8 + (lane & 3);
    int n  = nt * 8 + (lane >> 2);
    float b0 = W[(size_t)k0 * CH + n];
    float b1 = W[(size_t)(k0 + 4) * CH + n];
    uint32_t t0, t1;
    asm("cvt.rna.tf32.f32 %0, %1;" : "=r"(t0) : "f"(b0));
    asm("cvt.rna.tf32.f32 %0, %1;" : "=r"(t1) : "f"(b1));
    g_wfrag[idx] = make_uint2(t0, t1);
}

// ---------------- GEMM via tf32 tensor cores --------------------------------
// g_t[N,128] = A[N,128] @ W[128,128]; A==nullptr -> read g_h.
// 128 threads (4 warps), 64 rows/block; warp does m16 x n128, k full.
__global__ __launch_bounds__(128)
void k_gemm_tc(const float* __restrict__ A_, int layer) {
    __shared__ float sA[GROWS][132];           // stride 132: conflict-free frags
    const float* __restrict__ A = (A_ != nullptr) ? A_ : (const float*)g_h;

    int tid = threadIdx.x, wid = tid >> 5, lane = tid & 31;
    int row0 = blockIdx.x * GROWS;

    // stage A tile (coalesced float4), zero-fill OOB rows
    #pragma unroll
    for (int i = tid; i < GROWS * 32; i += 128) {
        int r = i >> 5, c4 = (i & 31) << 2;
        int gr = row0 + r;
        float4 v = (gr < NN) ? *(const float4*)(A + (size_t)gr * CH + c4)
                             : make_float4(0.f, 0.f, 0.f, 0.f);
        *(float4*)&sA[r][c4] = v;
    }
    __syncthreads();

    int mrow = wid * 16;
    int g  = lane >> 2;        // group id 0..7
    int tg = lane & 3;         // thread-in-group

    float acc[16][4];
    #pragma unroll
    for (int nt = 0; nt < 16; nt++)
        #pragma unroll
        for (int j = 0; j < 4; j++) acc[nt][j] = 0.f;

    const uint2* __restrict__ wbase = g_wfrag + ((size_t)layer * 256) * 32 + lane;

    #pragma unroll 4
    for (int kc = 0; kc < 16; kc++) {
        int k0 = kc * 8 + tg;
        float a0f = sA[mrow + g][k0];
        float a1f = sA[mrow + g + 8][k0];
        float a2f = sA[mrow + g][k0 + 4];
        float a3f = sA[mrow + g + 8][k0 + 4];
        uint32_t a0, a1, a2, a3;
        asm("cvt.rna.tf32.f32 %0, %1;" : "=r"(a0) : "f"(a0f));
        asm("cvt.rna.tf32.f32 %0, %1;" : "=r"(a1) : "f"(a1f));
        asm("cvt.rna.tf32.f32 %0, %1;" : "=r"(a2) : "f"(a2f));
        asm("cvt.rna.tf32.f32 %0, %1;" : "=r"(a3) : "f"(a3f));
        const uint2* wk = wbase + (size_t)(kc * 16) * 32;
        #pragma unroll
        for (int nt = 0; nt < 16; nt++) {
            uint2 b = wk[(size_t)nt * 32];
            asm volatile(
                "mma.sync.aligned.m16n8k8.row.col.f32.tf32.tf32.f32 "
                "{%0,%1,%2,%3}, {%4,%5,%6,%7}, {%8,%9}, {%0,%1,%2,%3};"
                : "+f"(acc[nt][0]), "+f"(acc[nt][1]),
                  "+f"(acc[nt][2]), "+f"(acc[nt][3])
                : "r"(a0), "r"(a1), "r"(a2), "r"(a3), "r"(b.x), "r"(b.y));
        }
    }

    // epilogue: c0/c1 -> row (mrow+g), cols nt*8 + 2*tg; c2/c3 -> row+8
    int gr0 = row0 + mrow + g;
    int gr1 = gr0 + 8;
    #pragma unroll
    for (int nt = 0; nt < 16; nt++) {
        int col = nt * 8 + 2 * tg;
        if (gr0 < NN)
            *(float2*)&g_t[(size_t)gr0 * CH + col] = make_float2(acc[nt][0], acc[nt][1]);
        if (gr1 < NN)
            *(float2*)&g_t[(size_t)gr1 * CH + col] = make_float2(acc[nt][2], acc[nt][3]);
    }
}

// ---------------- aggregation: h[i] = ReLU(sum_j w_j * t[col_j] + b) --------
// one warp per node; lane owns 4 channels (float4); 4-wide unroll for MLP
template <bool LAST>
__global__ __launch_bounds__(256)
void k_agg(const float* __restrict__ bias, const void* __restrict__ batch) {
    int node = (blockIdx.x * blockDim.x + threadIdx.x) >> 5;
    int lane = threadIdx.x & 31;
    if (node >= NN) return;
    int beg = g_rowptr[node];
    int end = g_rowptr[node + 1];
    int co = lane * 4;

    float ax = 0.f, ay = 0.f, az = 0.f, aw = 0.f;

    int j = beg;
    for (; j + 4 <= end; j += 4) {
        int2 e0 = g_edge[j];
        int2 e1 = g_edge[j + 1];
        int2 e2 = g_edge[j + 2];
        int2 e3 = g_edge[j + 3];
        float4 v0 = *(const float4*)(g_t + (size_t)e0.x * CH + co);
        float4 v1 = *(const float4*)(g_t + (size_t)e1.x * CH + co);
        float4 v2 = *(const float4*)(g_t + (size_t)e2.x * CH + co);
        float4 v3 = *(const float4*)(g_t + (size_t)e3.x * CH + co);
        float w0 = __int_as_float(e0.y), w1 = __int_as_float(e1.y);
        float w2 = __int_as_float(e2.y), w3 = __int_as_float(e3.y);
        ax = fmaf(w0, v0.x, ax); ay = fmaf(w0, v0.y, ay);
        az = fmaf(w0, v0.z, az); aw = fmaf(w0, v0.w, aw);
        ax = fmaf(w1, v1.x, ax); ay = fmaf(w1, v1.y, ay);
        az = fmaf(w1, v1.z, az); aw = fmaf(w1, v1.w, aw);
        ax = fmaf(w2, v2.x, ax); ay = fmaf(w2, v2.y, ay);
        az = fmaf(w2, v2.z, az); aw = fmaf(w2, v2.w, aw);
        ax = fmaf(w3, v3.x, ax); ay = fmaf(w3, v3.y, ay);
        az = fmaf(w3, v3.z, az); aw = fmaf(w3, v3.w, aw);
    }
    for (; j < end; j++) {
        int2 e0 = g_edge[j];
        float4 v0 = *(const float4*)(g_t + (size_t)e0.x * CH + co);
        float w0 = __int_as_float(e0.y);
        ax = fmaf(w0, v0.x, ax); ay = fmaf(w0, v0.y, ay);
        az = fmaf(w0, v0.z, az); aw = fmaf(w0, v0.w, aw);
    }

    float4 b = *(const float4*)(bias + co);
    ax = fmaxf(ax + b.x, 0.f);
    ay = fmaxf(ay + b.y, 0.f);
    az = fmaxf(az + b.z, 0.f);
    aw = fmaxf(aw + b.w, 0.f);

    *(float4*)(g_h + (size_t)node * CH + co) = make_float4(ax, ay, az, aw);

    if (LAST) {
        int g = ld_idx(batch, node, g_b64);
        float* pp = g_pool + g * CH + co;
        atomicAdd(pp + 0, ax);
        atomicAdd(pp + 1, ay);
        atomicAdd(pp + 2, az);
        atomicAdd(pp + 3, aw);
    }
}

// ---------------- head: out[g] = dot(pool[g], head_w) + head_b --------------
__global__ void k_head(const float* __restrict__ hw, const float* __restrict__ hb,
                       float* __restrict__ out) {
    int gid = (blockIdx.x * blockDim.x + threadIdx.x) >> 5;
    int lane = threadIdx.x & 31;
    if (gid >= NG) return;
    const float* p = g_pool + gid * CH;
    float s = p[lane]      * hw[lane]
            + p[lane + 32] * hw[lane + 32]
            + p[lane + 64] * hw[lane + 64]
            + p[lane + 96] * hw[lane + 96];
    #pragma unroll
    for (int o = 16; o; o >>= 1) s += __shfl_xor_sync(0xffffffffu, s, o);
    if (lane == 0) out[gid] = s + hb[0];
}

// ---------------- launch ----------------------------------------------------
extern "C" void kernel_launch(void* const* d_in, const int* in_sizes, int n_in,
                              void* d_out, int out_size) {
    // Inputs identified by UNIQUE element counts (order-proof).
    const float* x     = nullptr;
    const void*  ei    = nullptr;
    const void*  batch = nullptr;
    const float* Ws    = nullptr;
    const float* bs    = nullptr;
    const float* hw    = nullptr;
    const float* hb    = nullptr;
    for (int i = 0; i < n_in; i++) {
        switch (in_sizes[i]) {
            case 12800000: x     = (const float*)d_in[i]; break;
            case 3200000:  ei    = d_in[i];               break;
            case 100000:   batch = d_in[i];               break;
            case 49152:    Ws    = (const float*)d_in[i]; break;
            case 384:      bs    = (const float*)d_in[i]; break;
            case 128:      hw    = (const float*)d_in[i]; break;
            case 1:        hb    = (const float*)d_in[i]; break;
            default: break;
        }
    }
    float* out = (float*)d_out;

    const int T = 256;
    int gN = (NN + T - 1) / T;
    int gE = (NE + T - 1) / T;
    int gGemm = (NN + GROWS - 1) / GROWS;   // 1563 blocks of 128 threads
    int gAgg = (NN + 7) / 8;                // 8 warps per 256-thread block
    int gWf = (3 * 16 * 16 * 32 + 255) / 256;

    // dtype detection, W prepack, normalization + CSR (once, reused 3x)
    k_detect<<<1, 32>>>((const int*)ei, (const int*)batch);
    k_wfrag<<<gWf, T>>>(Ws);
    k_init<<<gN, T>>>();
    k_degree<<<gE, T>>>(ei);
    k_dinv<<<gN, T>>>();
    k_scan1<<<NB_SCAN, SCAN_T>>>();
    k_scan2<<<1, 128>>>();
    k_scan3<<<NB_SCAN, SCAN_T>>>();
    k_fill<<<gE, T>>>(ei);

    // layer 0
    k_gemm_tc<<<gGemm, 128>>>(x, 0);
    k_agg<false><<<gAgg, T>>>(bs + 0 * CH, batch);
    // layer 1 (A=nullptr -> read g_h)
    k_gemm_tc<<<gGemm, 128>>>(nullptr, 1);
    k_agg<false><<<gAgg, T>>>(bs + 1 * CH, batch);
    // layer 2 (fused global_add_pool in epilogue)
    k_gemm_tc<<<gGemm, 128>>>(nullptr, 2);
    k_agg<true><<<gAgg, T>>>(bs + 2 * CH, batch);

    // readout head
    k_head<<<(NG * 32 + T - 1) / T, T>>>(hw, hb, out);
}

// round 5
// speedup vs baseline: 1.5217x; 1.1208x over previous
#include <cuda_runtime.h>
#include <cuda_fp16.h>
#include <cstdint>

// Problem constants (fixed by the reference)
#define NN   100000
#define NE   1600000
#define CH   128
#define NG   512
#define TOT  (NE + NN)          // edges + self loops
#define SCAN_T 1024
#define NB_SCAN ((NN + SCAN_T - 1) / SCAN_T)   // 98
#define GROWS 64                 // GEMM rows per block

// ---------------- scratch (static __device__ allocations; allowed) ----------
__device__ __half g_th[(size_t)NN * CH];   // post-GEMM features (fp16 staging)
__device__ float g_h[(size_t)NN * CH];     // post-aggregation features (fp32)
__device__ float g_pool[NG * CH];          // global_add_pool accumulator
__device__ float g_dinv[NN];
__device__ int   g_cnt[NN];
__device__ int   g_rowptr[NN + 1];
__device__ int   g_fill[NN];
__device__ int2  g_edge[TOT];              // .x = src col, .y = weight bits
__device__ int   g_bsum[NB_SCAN];
__device__ int   g_boff[NB_SCAN];
__device__ int   g_ei64;                   // 1 if edge_index is int64, else int32
__device__ int   g_b64;                    // 1 if batch is int64, else int32
// B fragments in mma register order, tf32-converted:
// index = ((layer*16 + kc)*16 + nt)*32 + lane  -> uint2 {b0,b1}
__device__ uint2 g_wfrag[3 * 16 * 16 * 32];

// ---------------- dtype-agnostic index load ---------------------------------
__device__ __forceinline__ int ld_idx(const void* __restrict__ p, int i, int is64) {
    if (is64) return (int)((const long long*)p)[i];
    return ((const int*)p)[i];
}

// Detect int64 vs int32 (little-endian: int64 of small values has zero odd words).
__global__ void k_detect(const int* __restrict__ ei32, const int* __restrict__ b32) {
    if (threadIdx.x != 0 || blockIdx.x != 0) return;
    int e64 = 1;
    for (int k = 0; k < 64; k++)
        if (ei32[2 * k + 1] != 0) { e64 = 0; break; }
    g_ei64 = e64;
    int b64 = 1;
    for (int k = 0; k < 64; k++)
        if (b32[2 * (25000 + k) + 1] != 0) { b64 = 0; break; }
    g_b64 = b64;
}

// ---------------- graph preprocessing ---------------------------------------
__global__ void k_init() {
    int i = blockIdx.x * blockDim.x + threadIdx.x;
    if (i < NN) g_cnt[i] = 1;                 // self loop contributes 1 to degree
    if (i < NG * CH) g_pool[i] = 0.0f;
}

__global__ void k_degree(const void* __restrict__ ei) {
    int e = blockIdx.x * blockDim.x + threadIdx.x;
    if (e < NE) {
        int is64 = g_ei64;
        int d = ld_idx(ei, NE + e, is64);
        atomicAdd(&g_cnt[d], 1);
    }
}

// block-local exclusive scan of g_cnt -> g_rowptr (partial), block sums -> g_bsum
// also computes g_dinv (folded former k_dinv)
__global__ void k_scan1() {
    __shared__ int ws[32];
    int tid = threadIdx.x;
    int i = blockIdx.x * SCAN_T + tid;
    int v = (i < NN) ? g_cnt[i] : 0;
    if (i < NN) g_dinv[i] = rsqrtf((float)v);
    int lane = tid & 31, wid = tid >> 5;
    int x = v;
    #pragma unroll
    for (int o = 1; o < 32; o <<= 1) {
        int y = __shfl_up_sync(0xffffffffu, x, o);
        if (lane >= o) x += y;
    }
    if (lane == 31) ws[wid] = x;
    __syncthreads();
    if (wid == 0) {
        int s = ws[lane];
        #pragma unroll
        for (int o = 1; o < 32; o <<= 1) {
            int y = __shfl_up_sync(0xffffffffu, s, o);
            if (lane >= o) s += y;
        }
        ws[lane] = s;
    }
    __syncthreads();
    int off = wid ? ws[wid - 1] : 0;
    int incl = x + off;
    if (i < NN) g_rowptr[i] = incl - v;       // exclusive within block
    if (tid == SCAN_T - 1) g_bsum[blockIdx.x] = incl;
}

// exclusive scan of the 98 block sums
__global__ void k_scan2() {
    __shared__ int ws[4];
    int tid = threadIdx.x;
    int v = (tid < NB_SCAN) ? g_bsum[tid] : 0;
    int lane = tid & 31, wid = tid >> 5;
    int x = v;
    #pragma unroll
    for (int o = 1; o < 32; o <<= 1) {
        int y = __shfl_up_sync(0xffffffffu, x, o);
        if (lane >= o) x += y;
    }
    if (lane == 31) ws[wid] = x;
    __syncthreads();
    if (tid == 0) {
        int s = 0;
        #pragma unroll
        for (int k = 0; k < 4; k++) { int t = ws[k]; ws[k] = s; s += t; }
    }
    __syncthreads();
    if (tid < NB_SCAN) g_boff[tid] = x - v + ws[wid];
}

// finalize rowptr, write self-loop edge, init fill cursors
__global__ void k_scan3() {
    int tid = threadIdx.x;
    int i = blockIdx.x * SCAN_T + tid;
    if (i < NN) {
        int rp = g_rowptr[i] + g_boff[blockIdx.x];
        g_rowptr[i] = rp;
        float di = g_dinv[i];
        g_edge[rp] = make_int2(i, __float_as_int(di * di));
        g_fill[i] = rp + 1;
    }
    if (i == 0) g_rowptr[NN] = TOT;
}

__global__ void k_fill(const void* __restrict__ ei) {
    int e = blockIdx.x * blockDim.x + threadIdx.x;
    if (e < NE) {
        int is64 = g_ei64;
        int s = ld_idx(ei, e, is64);
        int d = ld_idx(ei, NE + e, is64);
        int pos = atomicAdd(&g_fill[d], 1);
        g_edge[pos] = make_int2(s, __float_as_int(g_dinv[s] * g_dinv[d]));
    }
}

// ---------------- W prepack: B fragments for mma.m16n8k8.tf32 ----------------
// b0 = W[kc*8 + (lane&3)][nt*8 + (lane>>2)], b1 = same with k+4
__global__ void k_wfrag(const float* __restrict__ Ws) {
    int idx = blockIdx.x * 256 + threadIdx.x;
    if (idx >= 3 * 16 * 16 * 32) return;
    int lane = idx & 31;
    int nt   = (idx >> 5) & 15;
    int kc   = (idx >> 9) & 15;
    int l    = idx >> 13;
    const float* W = Ws + (size_t)l * CH * CH;
    int k0 = kc * 8 + (lane & 3);
    int n  = nt * 8 + (lane >> 2);
    float b0 = W[(size_t)k0 * CH + n];
    float b1 = W[(size_t)(k0 + 4) * CH + n];
    uint32_t t0, t1;
    asm("cvt.rna.tf32.f32 %0, %1;" : "=r"(t0) : "f"(b0));
    asm("cvt.rna.tf32.f32 %0, %1;" : "=r"(t1) : "f"(b1));
    g_wfrag[idx] = make_uint2(t0, t1);
}

// ---------------- GEMM via tf32 tensor cores --------------------------------
// g_th[N,128] = fp16(A[N,128] @ W[128,128]); A==nullptr -> read g_h.
// 128 threads (4 warps), 64 rows/block; warp does m16 x n128, k full.
__global__ __launch_bounds__(128)
void k_gemm_tc(const float* __restrict__ A_, int layer) {
    __shared__ float sA[GROWS][132];           // stride 132: conflict-free frags
    const float* __restrict__ A = (A_ != nullptr) ? A_ : (const float*)g_h;

    int tid = threadIdx.x, wid = tid >> 5, lane = tid & 31;
    int row0 = blockIdx.x * GROWS;

    // stage A tile (coalesced float4), zero-fill OOB rows
    #pragma unroll
    for (int i = tid; i < GROWS * 32; i += 128) {
        int r = i >> 5, c4 = (i & 31) << 2;
        int gr = row0 + r;
        float4 v = (gr < NN) ? *(const float4*)(A + (size_t)gr * CH + c4)
                             : make_float4(0.f, 0.f, 0.f, 0.f);
        *(float4*)&sA[r][c4] = v;
    }
    __syncthreads();

    int mrow = wid * 16;
    int g  = lane >> 2;        // group id 0..7
    int tg = lane & 3;         // thread-in-group

    float acc[16][4];
    #pragma unroll
    for (int nt = 0; nt < 16; nt++)
        #pragma unroll
        for (int j = 0; j < 4; j++) acc[nt][j] = 0.f;

    const uint2* __restrict__ wbase = g_wfrag + ((size_t)layer * 256) * 32 + lane;

    #pragma unroll 4
    for (int kc = 0; kc < 16; kc++) {
        int k0 = kc * 8 + tg;
        float a0f = sA[mrow + g][k0];
        float a1f = sA[mrow + g + 8][k0];
        float a2f = sA[mrow + g][k0 + 4];
        float a3f = sA[mrow + g + 8][k0 + 4];
        uint32_t a0, a1, a2, a3;
        asm("cvt.rna.tf32.f32 %0, %1;" : "=r"(a0) : "f"(a0f));
        asm("cvt.rna.tf32.f32 %0, %1;" : "=r"(a1) : "f"(a1f));
        asm("cvt.rna.tf32.f32 %0, %1;" : "=r"(a2) : "f"(a2f));
        asm("cvt.rna.tf32.f32 %0, %1;" : "=r"(a3) : "f"(a3f));
        const uint2* wk = wbase + (size_t)(kc * 16) * 32;
        #pragma unroll
        for (int nt = 0; nt < 16; nt++) {
            uint2 b = wk[(size_t)nt * 32];
            asm volatile(
                "mma.sync.aligned.m16n8k8.row.col.f32.tf32.tf32.f32 "
                "{%0,%1,%2,%3}, {%4,%5,%6,%7}, {%8,%9}, {%0,%1,%2,%3};"
                : "+f"(acc[nt][0]), "+f"(acc[nt][1]),
                  "+f"(acc[nt][2]), "+f"(acc[nt][3])
                : "r"(a0), "r"(a1), "r"(a2), "r"(a3), "r"(b.x), "r"(b.y));
        }
    }

    // epilogue: c0/c1 -> row (mrow+g), cols nt*8 + 2*tg; c2/c3 -> row+8
    // store as fp16 (half2 per pair)
    int gr0 = row0 + mrow + g;
    int gr1 = gr0 + 8;
    #pragma unroll
    for (int nt = 0; nt < 16; nt++) {
        int col = nt * 8 + 2 * tg;
        if (gr0 < NN)
            *(__half2*)&g_th[(size_t)gr0 * CH + col] =
                __floats2half2_rn(acc[nt][0], acc[nt][1]);
        if (gr1 < NN)
            *(__half2*)&g_th[(size_t)gr1 * CH + col] =
                __floats2half2_rn(acc[nt][2], acc[nt][3]);
    }
}

// ---------------- aggregation: h[i] = ReLU(sum_j w_j * t[col_j] + b) --------
// one warp per node; lane owns 4 channels; fp16 gather, fp32 math
template <bool LAST>
__global__ __launch_bounds__(256)
void k_agg(const float* __restrict__ bias, const void* __restrict__ batch) {
    int node = (blockIdx.x * blockDim.x + threadIdx.x) >> 5;
    int lane = threadIdx.x & 31;
    if (node >= NN) return;
    int beg = g_rowptr[node];
    int end = g_rowptr[node + 1];
    int co = lane * 4;
    const __half* tb = (const __half*)g_th;

    float ax = 0.f, ay = 0.f, az = 0.f, aw = 0.f;

    int j = beg;
    for (; j + 4 <= end; j += 4) {
        int2 e0 = g_edge[j];
        int2 e1 = g_edge[j + 1];
        int2 e2 = g_edge[j + 2];
        int2 e3 = g_edge[j + 3];
        uint2 r0 = *(const uint2*)(tb + (size_t)e0.x * CH + co);
        uint2 r1 = *(const uint2*)(tb + (size_t)e1.x * CH + co);
        uint2 r2 = *(const uint2*)(tb + (size_t)e2.x * CH + co);
        uint2 r3 = *(const uint2*)(tb + (size_t)e3.x * CH + co);
        float w0 = __int_as_float(e0.y), w1 = __int_as_float(e1.y);
        float w2 = __int_as_float(e2.y), w3 = __int_as_float(e3.y);
        float2 a0 = __half22float2(*(__half2*)&r0.x), b0 = __half22float2(*(__half2*)&r0.y);
        float2 a1 = __half22float2(*(__half2*)&r1.x), b1 = __half22float2(*(__half2*)&r1.y);
        float2 a2 = __half22float2(*(__half2*)&r2.x), b2 = __half22float2(*(__half2*)&r2.y);
        float2 a3 = __half22float2(*(__half2*)&r3.x), b3 = __half22float2(*(__half2*)&r3.y);
        ax = fmaf(w0, a0.x, ax); ay = fmaf(w0, a0.y, ay);
        az = fmaf(w0, b0.x, az); aw = fmaf(w0, b0.y, aw);
        ax = fmaf(w1, a1.x, ax); ay = fmaf(w1, a1.y, ay);
        az = fmaf(w1, b1.x, az); aw = fmaf(w1, b1.y, aw);
        ax = fmaf(w2, a2.x, ax); ay = fmaf(w2, a2.y, ay);
        az = fmaf(w2, b2.x, az); aw = fmaf(w2, b2.y, aw);
        ax = fmaf(w3, a3.x, ax); ay = fmaf(w3, a3.y, ay);
        az = fmaf(w3, b3.x, az); aw = fmaf(w3, b3.y, aw);
    }
    for (; j < end; j++) {
        int2 e0 = g_edge[j];
        uint2 r0 = *(const uint2*)(tb + (size_t)e0.x * CH + co);
        float w0 = __int_as_float(e0.y);
        float2 a0 = __half22float2(*(__half2*)&r0.x), b0 = __half22float2(*(__half2*)&r0.y);
        ax = fmaf(w0, a0.x, ax); ay = fmaf(w0, a0.y, ay);
        az = fmaf(w0, b0.x, az); aw = fmaf(w0, b0.y, aw);
    }

    float4 b = *(const float4*)(bias + co);
    ax = fmaxf(ax + b.x, 0.f);
    ay = fmaxf(ay + b.y, 0.f);
    az = fmaxf(az + b.z, 0.f);
    aw = fmaxf(aw + b.w, 0.f);

    *(float4*)(g_h + (size_t)node * CH + co) = make_float4(ax, ay, az, aw);

    if (LAST) {
        int g = ld_idx(batch, node, g_b64);
        float* pp = g_pool + g * CH + co;
        atomicAdd(pp + 0, ax);
        atomicAdd(pp + 1, ay);
        atomicAdd(pp + 2, az);
        atomicAdd(pp + 3, aw);
    }
}

// ---------------- head: out[g] = dot(pool[g], head_w) + head_b --------------
__global__ void k_head(const float* __restrict__ hw, const float* __restrict__ hb,
                       float* __restrict__ out) {
    int gid = (blockIdx.x * blockDim.x + threadIdx.x) >> 5;
    int lane = threadIdx.x & 31;
    if (gid >= NG) return;
    const float* p = g_pool + gid * CH;
    float s = p[lane]      * hw[lane]
            + p[lane + 32] * hw[lane + 32]
            + p[lane + 64] * hw[lane + 64]
            + p[lane + 96] * hw[lane + 96];
    #pragma unroll
    for (int o = 16; o; o >>= 1) s += __shfl_xor_sync(0xffffffffu, s, o);
    if (lane == 0) out[gid] = s + hb[0];
}

// ---------------- launch ----------------------------------------------------
extern "C" void kernel_launch(void* const* d_in, const int* in_sizes, int n_in,
                              void* d_out, int out_size) {
    // Inputs identified by UNIQUE element counts (order-proof).
    const float* x     = nullptr;
    const void*  ei    = nullptr;
    const void*  batch = nullptr;
    const float* Ws    = nullptr;
    const float* bs    = nullptr;
    const float* hw    = nullptr;
    const float* hb    = nullptr;
    for (int i = 0; i < n_in; i++) {
        switch (in_sizes[i]) {
            case 12800000: x     = (const float*)d_in[i]; break;
            case 3200000:  ei    = d_in[i];               break;
            case 100000:   batch = d_in[i];               break;
            case 49152:    Ws    = (const float*)d_in[i]; break;
            case 384:      bs    = (const float*)d_in[i]; break;
            case 128:      hw    = (const float*)d_in[i]; break;
            case 1:        hb    = (const float*)d_in[i]; break;
            default: break;
        }
    }
    float* out = (float*)d_out;

    const int T = 256;
    int gN = (NN + T - 1) / T;
    int gE = (NE + T - 1) / T;
    int gGemm = (NN + GROWS - 1) / GROWS;   // 1563 blocks of 128 threads
    int gAgg = (NN + 7) / 8;                // 8 warps per 256-thread block
    int gWf = (3 * 16 * 16 * 32 + 255) / 256;

    // dtype detection, W prepack, normalization + CSR (once, reused 3x)
    k_detect<<<1, 32>>>((const int*)ei, (const int*)batch);
    k_wfrag<<<gWf, T>>>(Ws);
    k_init<<<gN, T>>>();
    k_degree<<<gE, T>>>(ei);
    k_scan1<<<NB_SCAN, SCAN_T>>>();
    k_scan2<<<1, 128>>>();
    k_scan3<<<NB_SCAN, SCAN_T>>>();
    k_fill<<<gE, T>>>(ei);

    // layer 0
    k_gemm_tc<<<gGemm, 128>>>(x, 0);
    k_agg<false><<<gAgg, T>>>(bs + 0 * CH, batch);
    // layer 1 (A=nullptr -> read g_h)
    k_gemm_tc<<<gGemm, 128>>>(nullptr, 1);
    k_agg<false><<<gAgg, T>>>(bs + 1 * CH, batch);
    // layer 2 (fused global_add_pool in epilogue)
    k_gemm_tc<<<gGemm, 128>>>(nullptr, 2);
    k_agg<true><<<gAgg, T>>>(bs + 2 * CH, batch);

    // readout head
    k_head<<<(NG * 32 + T - 1) / T, T>>>(hw, hb, out);
}